// round 1
// baseline (speedup 1.0000x reference)
#include <cuda_runtime.h>
#include <cuda_bf16.h>

// GCNConv: out = A_coo @ (X @ W) + bias
// Inputs (metadata order):
//   d_in[0] = x           float32 [N=100000, 64]
//   d_in[1] = edge_index  int32   [2, E=1600000]  (row 0 = dst, row 1 = src)
//   d_in[2] = edge_weight float32 [E]
//   d_in[3] = weight      float32 [64, 64]
//   d_in[4] = bias        float32 [64]
// Output: float32 [N, 64]

#define D_FEAT 64
#define MAX_N 100000

// Scratch for support = X @ W  (allocation-free: __device__ global)
__device__ float g_support[MAX_N * D_FEAT];

// ---------------------------------------------------------------------------
// Kernel 1: support = X @ W
// Block = 256 threads. Each thread computes a 4-row x 16-col register tile.
// W (64x64 fp32, 16 KB) staged in shared memory.
// ---------------------------------------------------------------------------
__global__ __launch_bounds__(256) void gemm_xw_kernel(
    const float* __restrict__ x,
    const float* __restrict__ w,
    float* __restrict__ sup,
    int N)
{
    __shared__ float Ws[D_FEAT * D_FEAT];  // [k][c] row-major, 16 KB

    int tid = threadIdx.x;
    // Load W coalesced as float4: 1024 float4 / 256 threads = 4 each
    #pragma unroll
    for (int i = 0; i < 4; i++) {
        int idx = tid + i * 256;
        reinterpret_cast<float4*>(Ws)[idx] =
            reinterpret_cast<const float4*>(w)[idx];
    }
    __syncthreads();

    int cg  = tid & 3;        // column group: 16 cols each
    int rg  = tid >> 2;       // 64 row groups per block
    int row0 = blockIdx.x * 256 + rg * 4;

    float acc[4][16];
    #pragma unroll
    for (int r = 0; r < 4; r++)
        #pragma unroll
        for (int c = 0; c < 16; c++)
            acc[r][c] = 0.0f;

    const int cbase = cg * 16;

    for (int k = 0; k < D_FEAT; k += 4) {
        // load x[row0..row0+3][k..k+3]
        float4 xv[4];
        #pragma unroll
        for (int r = 0; r < 4; r++) {
            int rr = row0 + r;
            if (rr < N)
                xv[r] = *reinterpret_cast<const float4*>(x + (size_t)rr * D_FEAT + k);
            else
                xv[r] = make_float4(0.f, 0.f, 0.f, 0.f);
        }
        #pragma unroll
        for (int kk = 0; kk < 4; kk++) {
            // load W[k+kk][cbase .. cbase+15]
            float4 wv[4];
            #pragma unroll
            for (int j = 0; j < 4; j++)
                wv[j] = *reinterpret_cast<const float4*>(&Ws[(k + kk) * D_FEAT + cbase + j * 4]);
            #pragma unroll
            for (int r = 0; r < 4; r++) {
                float xs = (kk == 0) ? xv[r].x : (kk == 1) ? xv[r].y
                         : (kk == 2) ? xv[r].z : xv[r].w;
                #pragma unroll
                for (int j = 0; j < 4; j++) {
                    acc[r][j * 4 + 0] = fmaf(xs, wv[j].x, acc[r][j * 4 + 0]);
                    acc[r][j * 4 + 1] = fmaf(xs, wv[j].y, acc[r][j * 4 + 1]);
                    acc[r][j * 4 + 2] = fmaf(xs, wv[j].z, acc[r][j * 4 + 2]);
                    acc[r][j * 4 + 3] = fmaf(xs, wv[j].w, acc[r][j * 4 + 3]);
                }
            }
        }
    }

    #pragma unroll
    for (int r = 0; r < 4; r++) {
        int rr = row0 + r;
        if (rr < N) {
            #pragma unroll
            for (int j = 0; j < 4; j++) {
                float4 v = make_float4(acc[r][j * 4 + 0], acc[r][j * 4 + 1],
                                       acc[r][j * 4 + 2], acc[r][j * 4 + 3]);
                *reinterpret_cast<float4*>(sup + (size_t)rr * D_FEAT + cbase + j * 4) = v;
            }
        }
    }
}

// ---------------------------------------------------------------------------
// Kernel 2: out[i][c] = bias[c]
// ---------------------------------------------------------------------------
__global__ __launch_bounds__(256) void init_bias_kernel(
    float* __restrict__ out,
    const float* __restrict__ bias,
    int total)  // N * 64
{
    __shared__ float bs[D_FEAT];
    if (threadIdx.x < D_FEAT) bs[threadIdx.x] = bias[threadIdx.x];
    __syncthreads();

    int idx = blockIdx.x * blockDim.x + threadIdx.x;
    // vectorized: 4 floats per thread
    int base = idx * 4;
    if (base + 3 < total) {
        int c = base & (D_FEAT - 1);
        float4 v = make_float4(bs[c], bs[c + 1], bs[c + 2], bs[c + 3]);
        *reinterpret_cast<float4*>(out + base) = v;
    } else {
        for (int i = base; i < total; i++)
            out[i] = bs[i & (D_FEAT - 1)];
    }
}

// ---------------------------------------------------------------------------
// Kernel 3: edge scatter. One warp per edge.
// Lane l handles features [2l, 2l+1]: coalesced 256B gather of the src row,
// scale by edge weight, atomicAdd into dst row.
// ---------------------------------------------------------------------------
__global__ __launch_bounds__(256) void edge_scatter_kernel(
    const int* __restrict__ edge_index,   // [2, E]
    const float* __restrict__ edge_weight,
    const float* __restrict__ sup,
    float* __restrict__ out,
    int E)
{
    int t = blockIdx.x * blockDim.x + threadIdx.x;
    int e = t >> 5;
    if (e >= E) return;
    int lane = t & 31;

    int dst = edge_index[e];        // row 0
    int src = edge_index[E + e];    // row 1
    float w = edge_weight[e];

    int f = lane * 2;
    float2 v = *reinterpret_cast<const float2*>(sup + (size_t)src * D_FEAT + f);
    float* o = out + (size_t)dst * D_FEAT + f;
    atomicAdd(o + 0, v.x * w);
    atomicAdd(o + 1, v.y * w);
}

// ---------------------------------------------------------------------------
extern "C" void kernel_launch(void* const* d_in, const int* in_sizes, int n_in,
                              void* d_out, int out_size)
{
    const float* x           = (const float*)d_in[0];
    const int*   edge_index  = (const int*)  d_in[1];
    const float* edge_weight = (const float*)d_in[2];
    const float* weight      = (const float*)d_in[3];
    const float* bias        = (const float*)d_in[4];
    float* out = (float*)d_out;

    const int N = in_sizes[0] / D_FEAT;
    const int E = in_sizes[2];

    float* sup = nullptr;
    cudaGetSymbolAddress((void**)&sup, g_support);

    // 1) out = bias (broadcast)  — independent of GEMM
    {
        int total = N * D_FEAT;
        int threads = 256;
        int blocks = (total / 4 + threads - 1) / threads;
        init_bias_kernel<<<blocks, threads>>>(out, bias, total);
    }

    // 2) support = X @ W
    {
        int blocks = (N + 255) / 256;
        gemm_xw_kernel<<<blocks, 256>>>(x, weight, sup, N);
    }

    // 3) scatter-add over edges (stream-ordered after 1 and 2)
    {
        long long totalThreads = (long long)E * 32;
        int threads = 256;
        long long blocks = (totalThreads + threads - 1) / threads;
        edge_scatter_kernel<<<(int)blocks, threads>>>(edge_index, edge_weight, sup, out, E);
    }
}

// round 2
// speedup vs baseline: 1.7686x; 1.7686x over previous
#include <cuda_runtime.h>
#include <cuda_bf16.h>

// GCNConv: out = A_coo @ (X @ W) + bias
// Strategy: support = X@W (reg-tiled GEMM) ; build CSR by dst per call
// (histogram + scan + scatter) ; warp-per-row SpMM with register accumulation
// (no output atomics), bias folded into the SpMM store.
//
// Inputs (metadata order):
//   d_in[0] = x           float32 [N=100000, 64]
//   d_in[1] = edge_index  int32   [2, E=1600000]  (row 0 = dst, row 1 = src)
//   d_in[2] = edge_weight float32 [E]
//   d_in[3] = weight      float32 [64, 64]
//   d_in[4] = bias        float32 [64]
// Output: float32 [N, 64]

#define D_FEAT 64
#define MAX_N 100000
#define MAX_E 1600000
#define SCAN_BLK 1024
#define MAX_NB ((MAX_N + SCAN_BLK - 1) / SCAN_BLK + 1)

// Allocation-free scratch (__device__ globals)
__device__ float g_support[MAX_N * D_FEAT];          // 25.6 MB
__device__ int2  g_edges[MAX_E];                     // {src, w-as-int}, 12.8 MB
__device__ int   g_count[MAX_N];
__device__ int   g_rowptr[MAX_N + 1];
__device__ int   g_cursor[MAX_N];
__device__ int   g_part[MAX_NB];
__device__ int   g_partscan[MAX_NB];

// ---------------------------------------------------------------------------
// Kernel 1: support = X @ W   (256 thr; 4-row x 16-col register tile/thread)
// ---------------------------------------------------------------------------
__global__ __launch_bounds__(256) void gemm_xw_kernel(
    const float* __restrict__ x,
    const float* __restrict__ w,
    float* __restrict__ sup,
    int N)
{
    __shared__ float Ws[D_FEAT * D_FEAT];

    int tid = threadIdx.x;
    #pragma unroll
    for (int i = 0; i < 4; i++) {
        int idx = tid + i * 256;
        reinterpret_cast<float4*>(Ws)[idx] =
            reinterpret_cast<const float4*>(w)[idx];
    }
    __syncthreads();

    int cg  = tid & 3;
    int rg  = tid >> 2;
    int row0 = blockIdx.x * 256 + rg * 4;

    float acc[4][16];
    #pragma unroll
    for (int r = 0; r < 4; r++)
        #pragma unroll
        for (int c = 0; c < 16; c++)
            acc[r][c] = 0.0f;

    const int cbase = cg * 16;

    for (int k = 0; k < D_FEAT; k += 4) {
        float4 xv[4];
        #pragma unroll
        for (int r = 0; r < 4; r++) {
            int rr = row0 + r;
            xv[r] = (rr < N)
                ? *reinterpret_cast<const float4*>(x + (size_t)rr * D_FEAT + k)
                : make_float4(0.f, 0.f, 0.f, 0.f);
        }
        #pragma unroll
        for (int kk = 0; kk < 4; kk++) {
            float4 wv[4];
            #pragma unroll
            for (int j = 0; j < 4; j++)
                wv[j] = *reinterpret_cast<const float4*>(&Ws[(k + kk) * D_FEAT + cbase + j * 4]);
            #pragma unroll
            for (int r = 0; r < 4; r++) {
                float xs = (kk == 0) ? xv[r].x : (kk == 1) ? xv[r].y
                         : (kk == 2) ? xv[r].z : xv[r].w;
                #pragma unroll
                for (int j = 0; j < 4; j++) {
                    acc[r][j * 4 + 0] = fmaf(xs, wv[j].x, acc[r][j * 4 + 0]);
                    acc[r][j * 4 + 1] = fmaf(xs, wv[j].y, acc[r][j * 4 + 1]);
                    acc[r][j * 4 + 2] = fmaf(xs, wv[j].z, acc[r][j * 4 + 2]);
                    acc[r][j * 4 + 3] = fmaf(xs, wv[j].w, acc[r][j * 4 + 3]);
                }
            }
        }
    }

    #pragma unroll
    for (int r = 0; r < 4; r++) {
        int rr = row0 + r;
        if (rr < N) {
            #pragma unroll
            for (int j = 0; j < 4; j++) {
                float4 v = make_float4(acc[r][j * 4 + 0], acc[r][j * 4 + 1],
                                       acc[r][j * 4 + 2], acc[r][j * 4 + 3]);
                *reinterpret_cast<float4*>(sup + (size_t)rr * D_FEAT + cbase + j * 4) = v;
            }
        }
    }
}

// ---------------------------------------------------------------------------
// CSR build
// ---------------------------------------------------------------------------
__global__ __launch_bounds__(SCAN_BLK) void zero_count_kernel(int N)
{
    int i = blockIdx.x * SCAN_BLK + threadIdx.x;
    if (i < N) g_count[i] = 0;
}

__global__ __launch_bounds__(256) void hist_kernel(
    const int* __restrict__ edge_index, int E)
{
    int t = blockIdx.x * 256 + threadIdx.x;
    if (t < E) atomicAdd(&g_count[edge_index[t]], 1);
}

// per-block sums
__global__ __launch_bounds__(SCAN_BLK) void scan_a_kernel(int N)
{
    __shared__ int wsum[32];
    int i = blockIdx.x * SCAN_BLK + threadIdx.x;
    int v = (i < N) ? g_count[i] : 0;
    // warp reduce
    #pragma unroll
    for (int o = 16; o > 0; o >>= 1) v += __shfl_down_sync(0xFFFFFFFFu, v, o);
    int lane = threadIdx.x & 31, wid = threadIdx.x >> 5;
    if (lane == 0) wsum[wid] = v;
    __syncthreads();
    if (wid == 0) {
        int s = wsum[lane];
        #pragma unroll
        for (int o = 16; o > 0; o >>= 1) s += __shfl_down_sync(0xFFFFFFFFu, s, o);
        if (lane == 0) g_part[blockIdx.x] = s;
    }
}

// exclusive scan of block sums (NB <= 99 — one thread is plenty)
__global__ void scan_b_kernel(int NB)
{
    if (threadIdx.x == 0 && blockIdx.x == 0) {
        int run = 0;
        for (int b = 0; b < NB; b++) {
            int t = g_part[b];
            g_partscan[b] = run;
            run += t;
        }
    }
}

// block-local exclusive scan + base -> rowptr & cursor
__global__ __launch_bounds__(SCAN_BLK) void scan_c_kernel(int N, int E)
{
    __shared__ int wsum[32];
    int i = blockIdx.x * SCAN_BLK + threadIdx.x;
    int c = (i < N) ? g_count[i] : 0;
    int lane = threadIdx.x & 31, wid = threadIdx.x >> 5;

    // inclusive warp scan
    int v = c;
    #pragma unroll
    for (int o = 1; o < 32; o <<= 1) {
        int n = __shfl_up_sync(0xFFFFFFFFu, v, o);
        if (lane >= o) v += n;
    }
    if (lane == 31) wsum[wid] = v;
    __syncthreads();
    if (wid == 0) {
        int s = wsum[lane];
        #pragma unroll
        for (int o = 1; o < 32; o <<= 1) {
            int n = __shfl_up_sync(0xFFFFFFFFu, s, o);
            if (lane >= o) s += n;
        }
        wsum[lane] = s;
    }
    __syncthreads();

    int excl = (v - c) + ((wid > 0) ? wsum[wid - 1] : 0) + g_partscan[blockIdx.x];
    if (i < N) {
        g_rowptr[i] = excl;
        g_cursor[i] = excl;
        if (i == N - 1) g_rowptr[N] = E;
    }
}

__global__ __launch_bounds__(256) void build_kernel(
    const int* __restrict__ edge_index,
    const float* __restrict__ edge_weight,
    int E)
{
    int t = blockIdx.x * 256 + threadIdx.x;
    if (t >= E) return;
    int dst = edge_index[t];
    int src = edge_index[E + t];
    float w = edge_weight[t];
    int pos = atomicAdd(&g_cursor[dst], 1);
    g_edges[pos] = make_int2(src, __float_as_int(w));
}

// ---------------------------------------------------------------------------
// SpMM: one warp per dst row, register accumulation, bias folded in.
// Lane l owns features [2l, 2l+1] (float2). Manual 2x unroll for MLP.
// ---------------------------------------------------------------------------
__global__ __launch_bounds__(256) void spmm_kernel(
    const float* __restrict__ sup,
    const float* __restrict__ bias,
    float* __restrict__ out,
    int N)
{
    int t = blockIdx.x * 256 + threadIdx.x;
    int row = t >> 5;
    if (row >= N) return;
    int lane = t & 31;
    int f = lane * 2;

    float2 acc = *reinterpret_cast<const float2*>(bias + f);

    int beg = g_rowptr[row];
    int end = g_rowptr[row + 1];

    int j = beg;
    for (; j + 1 < end; j += 2) {
        int2 e0 = g_edges[j];
        int2 e1 = g_edges[j + 1];
        float2 v0 = *reinterpret_cast<const float2*>(sup + (size_t)e0.x * D_FEAT + f);
        float2 v1 = *reinterpret_cast<const float2*>(sup + (size_t)e1.x * D_FEAT + f);
        float w0 = __int_as_float(e0.y);
        float w1 = __int_as_float(e1.y);
        acc.x = fmaf(v0.x, w0, acc.x);
        acc.y = fmaf(v0.y, w0, acc.y);
        acc.x = fmaf(v1.x, w1, acc.x);
        acc.y = fmaf(v1.y, w1, acc.y);
    }
    if (j < end) {
        int2 e0 = g_edges[j];
        float2 v0 = *reinterpret_cast<const float2*>(sup + (size_t)e0.x * D_FEAT + f);
        float w0 = __int_as_float(e0.y);
        acc.x = fmaf(v0.x, w0, acc.x);
        acc.y = fmaf(v0.y, w0, acc.y);
    }

    *reinterpret_cast<float2*>(out + (size_t)row * D_FEAT + f) = acc;
}

// ---------------------------------------------------------------------------
extern "C" void kernel_launch(void* const* d_in, const int* in_sizes, int n_in,
                              void* d_out, int out_size)
{
    const float* x           = (const float*)d_in[0];
    const int*   edge_index  = (const int*)  d_in[1];
    const float* edge_weight = (const float*)d_in[2];
    const float* weight      = (const float*)d_in[3];
    const float* bias        = (const float*)d_in[4];
    float* out = (float*)d_out;

    const int N = in_sizes[0] / D_FEAT;
    const int E = in_sizes[2];
    const int NB = (N + SCAN_BLK - 1) / SCAN_BLK;

    float* sup = nullptr;
    cudaGetSymbolAddress((void**)&sup, g_support);

    // CSR build pipeline (independent of GEMM until spmm)
    zero_count_kernel<<<NB, SCAN_BLK>>>(N);
    gemm_xw_kernel<<<(N + 255) / 256, 256>>>(x, weight, sup, N);
    hist_kernel<<<(E + 255) / 256, 256>>>(edge_index, E);
    scan_a_kernel<<<NB, SCAN_BLK>>>(N);
    scan_b_kernel<<<1, 32>>>(NB);
    scan_c_kernel<<<NB, SCAN_BLK>>>(N, E);
    build_kernel<<<(E + 255) / 256, 256>>>(edge_index, edge_weight, E);

    // SpMM (no atomics), bias folded
    spmm_kernel<<<(N * 32 + 255) / 256, 256>>>(sup, bias, out, N);
}